// round 15
// baseline (speedup 1.0000x reference)
#include <cuda_runtime.h>
#include <cuda_fp16.h>
#include <math.h>
#include <stdint.h>

// Problem constants
#define D_MODEL 1024
#define N_HEADS 16
#define DKH     64
#define BATCH   2
#define SEQ     2048
#define M_TOT   (BATCH * SEQ)   // 4096

// ---------------- scratch ----------------------------------------------------
__device__ __half g_Qh[M_TOT * D_MODEL];    // Q projection (fp16, row-major)
__device__ __half g_Kh[M_TOT * D_MODEL];    // K projection (fp16, row-major)
__device__ __half g_Vt[M_TOT * D_MODEL];    // V projection, per-head transposed
__device__ __half g_Ah[M_TOT * D_MODEL];    // flash output (fp16)
__device__ __half g_Xq[M_TOT * D_MODEL];
__device__ __half g_Xk[M_TOT * D_MODEL];
__device__ __half g_Xv[M_TOT * D_MODEL];
__device__ __half g_Wq[D_MODEL * D_MODEL];
__device__ __half g_Wk[D_MODEL * D_MODEL];
__device__ __half g_Wv[D_MODEL * D_MODEL];
__device__ __half g_Wo[D_MODEL * D_MODEL];

// ---------------- helpers ----------------------------------------------------
__device__ __forceinline__ void mma_f16(float* c, const unsigned* a, const unsigned* b) {
    asm volatile(
        "mma.sync.aligned.m16n8k16.row.col.f32.f16.f16.f32 "
        "{%0,%1,%2,%3}, {%4,%5,%6,%7}, {%8,%9}, {%0,%1,%2,%3};"
        : "+f"(c[0]), "+f"(c[1]), "+f"(c[2]), "+f"(c[3])
        : "r"(a[0]), "r"(a[1]), "r"(a[2]), "r"(a[3]), "r"(b[0]), "r"(b[1]));
}

// ---------------- pre-convert pass: fp32 -> fp16 ------------------------------
__global__ __launch_bounds__(256) void preconv_kernel(
    const float* __restrict__ i0, const float* __restrict__ i1, const float* __restrict__ i2,
    const float* __restrict__ w0, const float* __restrict__ w1,
    const float* __restrict__ w2, const float* __restrict__ w3,
    __half* __restrict__ o0, __half* __restrict__ o1, __half* __restrict__ o2,
    __half* __restrict__ o3, __half* __restrict__ o4, __half* __restrict__ o5,
    __half* __restrict__ o6)
{
    const int z = blockIdx.z;
    const float* src;
    __half* dst;
    int n4;
    switch (z) {
        case 0: src = i0; dst = o0; n4 = M_TOT * D_MODEL / 4; break;
        case 1: src = i1; dst = o1; n4 = M_TOT * D_MODEL / 4; break;
        case 2: src = i2; dst = o2; n4 = M_TOT * D_MODEL / 4; break;
        case 3: src = w0; dst = o3; n4 = D_MODEL * D_MODEL / 4; break;
        case 4: src = w1; dst = o4; n4 = D_MODEL * D_MODEL / 4; break;
        case 5: src = w2; dst = o5; n4 = D_MODEL * D_MODEL / 4; break;
        default: src = w3; dst = o6; n4 = D_MODEL * D_MODEL / 4; break;
    }
    const int idx    = blockIdx.x * 256 + threadIdx.x;
    const int stride = gridDim.x * 256;
    for (int i = idx; i < n4; i += stride) {
        float4 v = ((const float4*)src)[i];
        __half2 h0 = __floats2half2_rn(v.x, v.y);
        __half2 h1 = __floats2half2_rn(v.z, v.w);
        uint2 r;
        r.x = *(unsigned*)&h0;
        r.y = *(unsigned*)&h1;
        ((uint2*)dst)[i] = r;
    }
}

// ---------------- GEMM (fp16): Y = X[M,K] * W[N,K]^T + bias ------------------
// 256 thr / 8 warps, CTA tile 128x128, BK=64, warp tile 64x32.
// LDG.128 + STS.128 staging (cp.async is slow-path on Blackwell), double buffer,
// one barrier per chunk. Staging in two 16-reg batches to cap registers.
#define GSTR      72
#define GEMM_KC   64
#define GEMM_NCH  (D_MODEL / GEMM_KC)        // 16 chunks
#define GEMM_BUF  (128 * GSTR)
#define GEMM_SMEM (4 * GEMM_BUF * 2)         // 2 stages x 2 operands = 73728 B

template <int OUT_MODE>
__device__ __forceinline__ void gemm_body(
    const __half* __restrict__ X, const __half* __restrict__ W,
    const float* __restrict__ bias, void* __restrict__ Yv,
    __half* smem)
{
    const int N = D_MODEL, K = D_MODEL;

    __half* Xb[2] = { smem,                smem + GEMM_BUF };
    __half* Wb[2] = { smem + 2 * GEMM_BUF, smem + 3 * GEMM_BUF };

    const int tid  = threadIdx.x;
    const int warp = tid >> 5, lane = tid & 31;
    const int wm = warp >> 2, wn = warp & 3;
    const int g  = lane >> 2, tg = lane & 3;
    const int bm = blockIdx.y * 128, bn = blockIdx.x * 128;

    const int lr  = tid >> 1;          // row 0..127
    const int lhs = (tid & 1) * 32;    // half offset 0 / 32

    const __half* xg = X + (size_t)(bm + lr) * K + lhs;
    const __half* wg = W + (size_t)(bn + lr) * K + lhs;

    float c[4][4][4];
#pragma unroll
    for (int mf = 0; mf < 4; mf++)
#pragma unroll
        for (int nf = 0; nf < 4; nf++)
#pragma unroll
            for (int k = 0; k < 4; k++) c[mf][nf][k] = 0.f;

    // stage chunk ch into buffer buf: LDG.128 -> regs -> STS.128, 2 batches
    auto stage = [&](int ch, int buf) {
        const uint4* xp = (const uint4*)(xg + ch * GEMM_KC);
        const uint4* wp = (const uint4*)(wg + ch * GEMM_KC);
        uint4* xs = (uint4*)(Xb[buf] + lr * GSTR + lhs);
        uint4* ws = (uint4*)(Wb[buf] + lr * GSTR + lhs);
        {
            uint4 x0 = xp[0], x1 = xp[1];
            uint4 w0 = wp[0], w1 = wp[1];
            xs[0] = x0; xs[1] = x1;
            ws[0] = w0; ws[1] = w1;
        }
        {
            uint4 x2 = xp[2], x3 = xp[3];
            uint4 w2 = wp[2], w3 = wp[3];
            xs[2] = x2; xs[3] = x3;
            ws[2] = w2; ws[3] = w3;
        }
    };

    stage(0, 0);
    __syncthreads();

    for (int ch = 0; ch < GEMM_NCH; ch++) {
        const int buf = ch & 1;
        if (ch + 1 < GEMM_NCH) stage(ch + 1, buf ^ 1);

        const __half* Xs = Xb[buf];
        const __half* Ws = Wb[buf];
#pragma unroll
        for (int ks = 0; ks < 4; ks++) {
            unsigned a[4][4], b[4][2];
            const int kc = ks * 16 + tg * 2;
#pragma unroll
            for (int mf = 0; mf < 4; mf++) {
                int row = wm * 64 + mf * 16;
                a[mf][0] = *(const unsigned*)&Xs[(row + g    ) * GSTR + kc    ];
                a[mf][1] = *(const unsigned*)&Xs[(row + g + 8) * GSTR + kc    ];
                a[mf][2] = *(const unsigned*)&Xs[(row + g    ) * GSTR + kc + 8];
                a[mf][3] = *(const unsigned*)&Xs[(row + g + 8) * GSTR + kc + 8];
            }
#pragma unroll
            for (int nf = 0; nf < 4; nf++) {
                int col = wn * 32 + nf * 8 + g;
                b[nf][0] = *(const unsigned*)&Ws[col * GSTR + kc    ];
                b[nf][1] = *(const unsigned*)&Ws[col * GSTR + kc + 8];
            }
#pragma unroll
            for (int mf = 0; mf < 4; mf++)
#pragma unroll
                for (int nf = 0; nf < 4; nf++)
                    mma_f16(c[mf][nf], a[mf], b[nf]);
        }
        __syncthreads();
    }

    // epilogue
#pragma unroll
    for (int mf = 0; mf < 4; mf++) {
#pragma unroll
        for (int nf = 0; nf < 4; nf++) {
            int row = bm + wm * 64 + mf * 16 + g;
            int col = bn + wn * 32 + nf * 8 + 2 * tg;
            float b0 = bias[col], b1 = bias[col + 1];
            float v0 = c[mf][nf][0] + b0, v1 = c[mf][nf][1] + b1;
            float v2 = c[mf][nf][2] + b0, v3 = c[mf][nf][3] + b1;
            if (OUT_MODE == 0) {
                float* Y = (float*)Yv;
                *(float2*)(Y + (size_t)row * N + col)       = make_float2(v0, v1);
                *(float2*)(Y + (size_t)(row + 8) * N + col) = make_float2(v2, v3);
            } else if (OUT_MODE == 1) {
                __half* Y = (__half*)Yv;
                *(__half2*)(Y + (size_t)row * N + col)       = __floats2half2_rn(v0, v1);
                *(__half2*)(Y + (size_t)(row + 8) * N + col) = __floats2half2_rn(v2, v3);
            } else {
                // per-head transpose: Yt[((b*16+h)*64 + d)][s]
                __half* Y = (__half*)Yv;
                int bb = row >> 11, s = row & (SEQ - 1);
                int h  = col >> 6,  d = col & 63;
                size_t r0 = ((size_t)(bb * N_HEADS + h) * DKH + d) * SEQ;
                Y[r0 + s]            = __float2half_rn(v0);
                Y[r0 + SEQ + s]      = __float2half_rn(v1);   // d+1
                Y[r0 + s + 8]        = __float2half_rn(v2);
                Y[r0 + SEQ + s + 8]  = __float2half_rn(v3);
            }
        }
    }
}

// Fused QKV projection: z=0 -> Q (fp16), z=1 -> K (fp16), z=2 -> V (fp16 transposed)
__global__ __launch_bounds__(256, 2)
void gemm_qkv_kernel(const __half* __restrict__ X0, const __half* __restrict__ X1,
                     const __half* __restrict__ X2,
                     const __half* __restrict__ W0, const __half* __restrict__ W1,
                     const __half* __restrict__ W2,
                     const float* __restrict__ b0, const float* __restrict__ b1,
                     const float* __restrict__ b2,
                     __half* __restrict__ Y0, __half* __restrict__ Y1,
                     __half* __restrict__ Y2)
{
    extern __shared__ __half gsm[];
    const int z = blockIdx.z;
    if (z == 2) {
        gemm_body<2>(X2, W2, b2, Y2, gsm);
    } else if (z == 1) {
        gemm_body<1>(X1, W1, b1, Y1, gsm);
    } else {
        gemm_body<1>(X0, W0, b0, Y0, gsm);
    }
}

// O-projection: fp32 output (final result).
__global__ __launch_bounds__(256, 2)
void gemm_one_kernel(const __half* __restrict__ X, const __half* __restrict__ W,
                     const float* __restrict__ bias, float* __restrict__ Y)
{
    extern __shared__ __half gsm[];
    gemm_body<0>(X, W, bias, Y, gsm);
}

// ---------------- flash attention, fp16 mma (BQ=64) --------------------------
// 128 thr / 4 warps, 64 q-rows per block, KV tiles of 64. LDG+STS staging.
#define PSTRH 72
#define KSTRH 72
#define VSTRH 72
#define FLASH_SMEM ((64 * PSTRH + 64 * KSTRH + 64 * VSTRH) * 2)   // 27648 B

__global__ __launch_bounds__(128, 4)
void flash_f16_kernel()
{
    extern __shared__ __half fsm[];
    __half* Ph  = fsm;                    // [64][PSTRH]  Q staging, then P
    __half* Kh  = Ph + 64 * PSTRH;        // [64][KSTRH]  K tile
    __half* Vth = Kh + 64 * KSTRH;        // [64][VSTRH]  Vt tile (row=d, col=key)

    const int tid  = threadIdx.x;
    const int warp = tid >> 5, lane = tid & 31;
    const int g = lane >> 2, tg = lane & 3;
    const int qt = (int)gridDim.x - 1 - (int)blockIdx.x;   // heavy blocks first
    const int bh = blockIdx.y;
    const int b  = bh >> 4, h = bh & 15;
    const int qbase = qt * 64;
    const int row0  = warp * 16;

    const size_t base  = (size_t)b * SEQ * D_MODEL + (size_t)h * DKH;
    const __half* Qg  = g_Qh + base;
    const __half* Kg  = g_Kh + base;
    const __half* Vtg = g_Vt + (size_t)(b * N_HEADS + h) * DKH * SEQ;

    const int sr = tid >> 3;          // staging row 0..15
    const int sc = (tid & 7) * 8;     // staging col (halves) 0..56

    // ---- stage Q (LDG + STS) ----
    {
        uint4* ps = (uint4*)(Ph + sr * PSTRH + sc);
#pragma unroll
        for (int p = 0; p < 4; p += 2) {
            uint4 q0 = *(const uint4*)(Qg + (size_t)(qbase + sr + 16 * p) * D_MODEL + sc);
            uint4 q1 = *(const uint4*)(Qg + (size_t)(qbase + sr + 16 * (p + 1)) * D_MODEL + sc);
            *(uint4*)((char*)ps + 16 * p * PSTRH * 2)       = q0;
            *(uint4*)((char*)ps + 16 * (p + 1) * PSTRH * 2) = q1;
        }
    }
    __syncthreads();

    // ---- extract Q fragments (warp's 16 rows) ----
    unsigned qf[4][4];
#pragma unroll
    for (int ks = 0; ks < 4; ks++) {
        const int kc = ks * 16 + tg * 2;
        qf[ks][0] = *(const unsigned*)&Ph[(row0 + g    ) * PSTRH + kc    ];
        qf[ks][1] = *(const unsigned*)&Ph[(row0 + g + 8) * PSTRH + kc    ];
        qf[ks][2] = *(const unsigned*)&Ph[(row0 + g    ) * PSTRH + kc + 8];
        qf[ks][3] = *(const unsigned*)&Ph[(row0 + g + 8) * PSTRH + kc + 8];
    }

    float O[8][4];
#pragma unroll
    for (int nf = 0; nf < 8; nf++)
#pragma unroll
        for (int k = 0; k < 4; k++) O[nf][k] = 0.f;
    float m0 = -1e30f, m1 = -1e30f, l0 = 0.f, l1 = 0.f;

    const int q0r = qbase + row0 + g;
    const int q1r = q0r + 8;

    const int nkt = qt + 1;
    for (int kt = 0; kt < nkt; kt++) {
        const int kbase = kt * 64;
        __syncthreads();
        // ---- stage K and Vt (LDG + STS, two batches) ----
        {
            uint4* ks_ = (uint4*)(Kh  + sr * KSTRH + sc);
            uint4* vs_ = (uint4*)(Vth + sr * VSTRH + sc);
            {
                uint4 k0 = *(const uint4*)(Kg  + (size_t)(kbase + sr) * D_MODEL + sc);
                uint4 k1 = *(const uint4*)(Kg  + (size_t)(kbase + sr + 16) * D_MODEL + sc);
                uint4 v0 = *(const uint4*)(Vtg + (size_t)sr * SEQ + kbase + sc);
                uint4 v1 = *(const uint4*)(Vtg + (size_t)(sr + 16) * SEQ + kbase + sc);
                *(uint4*)((char*)ks_)                       = k0;
                *(uint4*)((char*)ks_ + 16 * KSTRH * 2)      = k1;
                *(uint4*)((char*)vs_)                       = v0;
                *(uint4*)((char*)vs_ + 16 * VSTRH * 2)      = v1;
            }
            {
                uint4 k2 = *(const uint4*)(Kg  + (size_t)(kbase + sr + 32) * D_MODEL + sc);
                uint4 k3 = *(const uint4*)(Kg  + (size_t)(kbase + sr + 48) * D_MODEL + sc);
                uint4 v2 = *(const uint4*)(Vtg + (size_t)(sr + 32) * SEQ + kbase + sc);
                uint4 v3 = *(const uint4*)(Vtg + (size_t)(sr + 48) * SEQ + kbase + sc);
                *(uint4*)((char*)ks_ + 32 * KSTRH * 2)      = k2;
                *(uint4*)((char*)ks_ + 48 * KSTRH * 2)      = k3;
                *(uint4*)((char*)vs_ + 32 * VSTRH * 2)      = v2;
                *(uint4*)((char*)vs_ + 48 * VSTRH * 2)      = v3;
            }
        }
        __syncthreads();

        // ---- S = Q K^T ----
        float S[8][4];
#pragma unroll
        for (int nf = 0; nf < 8; nf++)
#pragma unroll
            for (int k = 0; k < 4; k++) S[nf][k] = 0.f;

#pragma unroll
        for (int ks = 0; ks < 4; ks++) {
            const int kc = ks * 16 + tg * 2;
#pragma unroll
            for (int nf = 0; nf < 8; nf++) {
                unsigned bb[2];
                bb[0] = *(const unsigned*)&Kh[(nf * 8 + g) * KSTRH + kc    ];
                bb[1] = *(const unsigned*)&Kh[(nf * 8 + g) * KSTRH + kc + 8];
                mma_f16(S[nf], qf[ks], bb);
            }
        }

        // ---- scale + causal mask ----
        const bool diag = (kt == qt);
#pragma unroll
        for (int nf = 0; nf < 8; nf++) {
            int kc0 = kbase + nf * 8 + 2 * tg;
            S[nf][0] *= 0.125f; S[nf][1] *= 0.125f;
            S[nf][2] *= 0.125f; S[nf][3] *= 0.125f;
            if (diag) {
                if (kc0     > q0r) S[nf][0] = -1e30f;
                if (kc0 + 1 > q0r) S[nf][1] = -1e30f;
                if (kc0     > q1r) S[nf][2] = -1e30f;
                if (kc0 + 1 > q1r) S[nf][3] = -1e30f;
            }
        }

        // ---- online softmax ----
        float mx0 = -1e30f, mx1 = -1e30f;
#pragma unroll
        for (int nf = 0; nf < 8; nf++) {
            mx0 = fmaxf(mx0, fmaxf(S[nf][0], S[nf][1]));
            mx1 = fmaxf(mx1, fmaxf(S[nf][2], S[nf][3]));
        }
        mx0 = fmaxf(mx0, __shfl_xor_sync(0xffffffffu, mx0, 1));
        mx0 = fmaxf(mx0, __shfl_xor_sync(0xffffffffu, mx0, 2));
        mx1 = fmaxf(mx1, __shfl_xor_sync(0xffffffffu, mx1, 1));
        mx1 = fmaxf(mx1, __shfl_xor_sync(0xffffffffu, mx1, 2));

        float mn0 = fmaxf(m0, mx0), mn1 = fmaxf(m1, mx1);
        float fac0 = __expf(m0 - mn0), fac1 = __expf(m1 - mn1);

        float s0 = 0.f, s1 = 0.f;
#pragma unroll
        for (int nf = 0; nf < 8; nf++) {
            S[nf][0] = __expf(S[nf][0] - mn0);
            S[nf][1] = __expf(S[nf][1] - mn0);
            S[nf][2] = __expf(S[nf][2] - mn1);
            S[nf][3] = __expf(S[nf][3] - mn1);
            s0 += S[nf][0] + S[nf][1];
            s1 += S[nf][2] + S[nf][3];
        }
        s0 += __shfl_xor_sync(0xffffffffu, s0, 1);
        s0 += __shfl_xor_sync(0xffffffffu, s0, 2);
        s1 += __shfl_xor_sync(0xffffffffu, s1, 1);
        s1 += __shfl_xor_sync(0xffffffffu, s1, 2);

        l0 = l0 * fac0 + s0; l1 = l1 * fac1 + s1;
        m0 = mn0; m1 = mn1;
#pragma unroll
        for (int nf = 0; nf < 8; nf++) {
            O[nf][0] *= fac0; O[nf][1] *= fac0;
            O[nf][2] *= fac1; O[nf][3] *= fac1;
        }

        // ---- P -> smem fp16 (per-warp rows) ----
#pragma unroll
        for (int nf = 0; nf < 8; nf++) {
            int col = nf * 8 + 2 * tg;
            *(__half2*)&Ph[(row0 + g    ) * PSTRH + col] = __floats2half2_rn(S[nf][0], S[nf][1]);
            *(__half2*)&Ph[(row0 + g + 8) * PSTRH + col] = __floats2half2_rn(S[nf][2], S[nf][3]);
        }
        __syncwarp();

        // ---- O += P V ----
#pragma unroll
        for (int ks = 0; ks < 4; ks++) {
            const int kc = ks * 16 + tg * 2;
            unsigned a[4];
            a[0] = *(const unsigned*)&Ph[(row0 + g    ) * PSTRH + kc    ];
            a[1] = *(const unsigned*)&Ph[(row0 + g + 8) * PSTRH + kc    ];
            a[2] = *(const unsigned*)&Ph[(row0 + g    ) * PSTRH + kc + 8];
            a[3] = *(const unsigned*)&Ph[(row0 + g + 8) * PSTRH + kc + 8];
#pragma unroll
            for (int nf = 0; nf < 8; nf++) {
                unsigned bb[2];
                bb[0] = *(const unsigned*)&Vth[(nf * 8 + g) * VSTRH + kc    ];
                bb[1] = *(const unsigned*)&Vth[(nf * 8 + g) * VSTRH + kc + 8];
                mma_f16(O[nf], a, bb);
            }
        }
        __syncwarp();
    }

    // ---- normalize + write fp16 ----
    float inv0 = 1.0f / l0, inv1 = 1.0f / l1;
    __half* Ag = g_Ah + base;
#pragma unroll
    for (int nf = 0; nf < 8; nf++) {
        int col = nf * 8 + 2 * tg;
        *(__half2*)(Ag + (size_t)q0r * D_MODEL + col) =
            __floats2half2_rn(O[nf][0] * inv0, O[nf][1] * inv0);
        *(__half2*)(Ag + (size_t)q1r * D_MODEL + col) =
            __floats2half2_rn(O[nf][2] * inv1, O[nf][3] * inv1);
    }
}

// ---------------- launch -----------------------------------------------------
extern "C" void kernel_launch(void* const* d_in, const int* in_sizes, int n_in,
                              void* d_out, int out_size)
{
    (void)in_sizes; (void)n_in; (void)out_size;
    const float* in_Q = (const float*)d_in[0];
    const float* in_K = (const float*)d_in[1];
    const float* in_V = (const float*)d_in[2];
    const float* Wq   = (const float*)d_in[3];
    const float* bq   = (const float*)d_in[4];
    const float* Wk   = (const float*)d_in[5];
    const float* bk   = (const float*)d_in[6];
    const float* Wv   = (const float*)d_in[7];
    const float* bv   = (const float*)d_in[8];
    const float* Wo   = (const float*)d_in[9];
    const float* bo   = (const float*)d_in[10];
    float* out = (float*)d_out;

    __half *qh, *kh, *vt, *ah, *xq, *xk, *xv, *wq, *wk, *wv, *wo;
    cudaGetSymbolAddress((void**)&qh, g_Qh);
    cudaGetSymbolAddress((void**)&kh, g_Kh);
    cudaGetSymbolAddress((void**)&vt, g_Vt);
    cudaGetSymbolAddress((void**)&ah, g_Ah);
    cudaGetSymbolAddress((void**)&xq, g_Xq);
    cudaGetSymbolAddress((void**)&xk, g_Xk);
    cudaGetSymbolAddress((void**)&xv, g_Xv);
    cudaGetSymbolAddress((void**)&wq, g_Wq);
    cudaGetSymbolAddress((void**)&wk, g_Wk);
    cudaGetSymbolAddress((void**)&wv, g_Wv);
    cudaGetSymbolAddress((void**)&wo, g_Wo);

    cudaFuncSetAttribute(gemm_qkv_kernel,
                         cudaFuncAttributeMaxDynamicSharedMemorySize, GEMM_SMEM);
    cudaFuncSetAttribute(gemm_one_kernel,
                         cudaFuncAttributeMaxDynamicSharedMemorySize, GEMM_SMEM);
    cudaFuncSetAttribute(flash_f16_kernel,
                         cudaFuncAttributeMaxDynamicSharedMemorySize, FLASH_SMEM);

    // 1) convert inputs + weights to fp16
    dim3 pc_grid(1024, 1, 7);
    preconv_kernel<<<pc_grid, 256>>>(in_Q, in_K, in_V, Wq, Wk, Wv, Wo,
                                     xq, xk, xv, wq, wk, wv, wo);

    // 2) fused QKV projections (fp16 outputs; V transposed per head)
    dim3 qkv_grid(D_MODEL / 128, M_TOT / 128, 3);   // (8, 32, 3)
    gemm_qkv_kernel<<<qkv_grid, 256, GEMM_SMEM>>>(
        xq, xk, xv, wq, wk, wv, bq, bk, bv, qh, kh, vt);

    // 3) flash attention (fp16; writes fp16 g_Ah)
    dim3 fgrid(SEQ / 64, BATCH * N_HEADS);          // (32, 32)
    flash_f16_kernel<<<fgrid, 128, FLASH_SMEM>>>();

    // 4) output projection (fp16 mma, fp32 result)
    dim3 o_grid(D_MODEL / 128, M_TOT / 128);        // (8, 32)
    gemm_one_kernel<<<o_grid, 256, GEMM_SMEM>>>(ah, wo, bo, out);
}

// round 17
// speedup vs baseline: 1.0940x; 1.0940x over previous
#include <cuda_runtime.h>
#include <cuda_fp16.h>
#include <math.h>
#include <stdint.h>

// Problem constants
#define D_MODEL 1024
#define N_HEADS 16
#define DKH     64
#define BATCH   2
#define SEQ     2048
#define M_TOT   (BATCH * SEQ)   // 4096

// ---------------- scratch ----------------------------------------------------
__device__ __half g_Qh[M_TOT * D_MODEL];    // Q projection (fp16, row-major)
__device__ __half g_Kh[M_TOT * D_MODEL];    // K projection (fp16, row-major)
__device__ __half g_Vt[M_TOT * D_MODEL];    // V projection, per-head transposed
__device__ __half g_Ah[M_TOT * D_MODEL];    // flash output (fp16)
__device__ __half g_Xq[M_TOT * D_MODEL];
__device__ __half g_Xk[M_TOT * D_MODEL];
__device__ __half g_Xv[M_TOT * D_MODEL];
__device__ __half g_Wq[D_MODEL * D_MODEL];
__device__ __half g_Wk[D_MODEL * D_MODEL];
__device__ __half g_Wv[D_MODEL * D_MODEL];
__device__ __half g_Wo[D_MODEL * D_MODEL];

// ---------------- helpers ----------------------------------------------------
__device__ __forceinline__ uint32_t s2u(const void* p) {
    uint32_t a;
    asm("{ .reg .u64 t; cvta.to.shared.u64 t, %1; cvt.u32.u64 %0, t; }"
        : "=r"(a) : "l"(p));
    return a;
}

__device__ __forceinline__ void cpa16(uint32_t s, const void* g) {
    asm volatile("cp.async.cg.shared.global [%0], [%1], 16;" :: "r"(s), "l"(g));
}

__device__ __forceinline__ void mma_f16(float* c, const unsigned* a, const unsigned* b) {
    asm volatile(
        "mma.sync.aligned.m16n8k16.row.col.f32.f16.f16.f32 "
        "{%0,%1,%2,%3}, {%4,%5,%6,%7}, {%8,%9}, {%0,%1,%2,%3};"
        : "+f"(c[0]), "+f"(c[1]), "+f"(c[2]), "+f"(c[3])
        : "r"(a[0]), "r"(a[1]), "r"(a[2]), "r"(a[3]), "r"(b[0]), "r"(b[1]));
}

// ---------------- pre-convert pass: fp32 -> fp16 ------------------------------
__global__ __launch_bounds__(256) void preconv_kernel(
    const float* __restrict__ i0, const float* __restrict__ i1, const float* __restrict__ i2,
    const float* __restrict__ w0, const float* __restrict__ w1,
    const float* __restrict__ w2, const float* __restrict__ w3,
    __half* __restrict__ o0, __half* __restrict__ o1, __half* __restrict__ o2,
    __half* __restrict__ o3, __half* __restrict__ o4, __half* __restrict__ o5,
    __half* __restrict__ o6)
{
    const int z = blockIdx.z;
    const float* src;
    __half* dst;
    int n4;
    switch (z) {
        case 0: src = i0; dst = o0; n4 = M_TOT * D_MODEL / 4; break;
        case 1: src = i1; dst = o1; n4 = M_TOT * D_MODEL / 4; break;
        case 2: src = i2; dst = o2; n4 = M_TOT * D_MODEL / 4; break;
        case 3: src = w0; dst = o3; n4 = D_MODEL * D_MODEL / 4; break;
        case 4: src = w1; dst = o4; n4 = D_MODEL * D_MODEL / 4; break;
        case 5: src = w2; dst = o5; n4 = D_MODEL * D_MODEL / 4; break;
        default: src = w3; dst = o6; n4 = D_MODEL * D_MODEL / 4; break;
    }
    const int idx    = blockIdx.x * 256 + threadIdx.x;
    const int stride = gridDim.x * 256;
    for (int i = idx; i < n4; i += stride) {
        float4 v = ((const float4*)src)[i];
        __half2 h0 = __floats2half2_rn(v.x, v.y);
        __half2 h1 = __floats2half2_rn(v.z, v.w);
        uint2 r;
        r.x = *(unsigned*)&h0;
        r.y = *(unsigned*)&h1;
        ((uint2*)dst)[i] = r;
    }
}

// ---------------- GEMM (fp16): Y = X[M,K] * W[N,K]^T + bias ------------------
// 256 thr / 8 warps, CTA tile 128x128, BK=64, warp tile 64x32.
// Software-pipelined staging: LDG batch -> 32 HMMAs -> STS batch (x2 per chunk).
// The MMA block between LDG and STS covers the global-load latency.
#define GSTR      72
#define GEMM_KC   64
#define GEMM_NCH  (D_MODEL / GEMM_KC)        // 16 chunks
#define GEMM_BUF  (128 * GSTR)
#define GEMM_SMEM (4 * GEMM_BUF * 2)         // 2 stages x 2 operands = 73728 B

template <int OUT_MODE>
__device__ __forceinline__ void gemm_body(
    const __half* __restrict__ X, const __half* __restrict__ W,
    const float* __restrict__ bias, void* __restrict__ Yv,
    __half* smem)
{
    const int N = D_MODEL, K = D_MODEL;

    __half* Xb[2] = { smem,                smem + GEMM_BUF };
    __half* Wb[2] = { smem + 2 * GEMM_BUF, smem + 3 * GEMM_BUF };

    const int tid  = threadIdx.x;
    const int warp = tid >> 5, lane = tid & 31;
    const int wm = warp >> 2, wn = warp & 3;
    const int g  = lane >> 2, tg = lane & 3;
    const int bm = blockIdx.y * 128, bn = blockIdx.x * 128;

    const int lr  = tid >> 1;          // row 0..127
    const int lhs = (tid & 1) * 32;    // half offset 0 / 32

    const __half* xg = X + (size_t)(bm + lr) * K + lhs;
    const __half* wg = W + (size_t)(bn + lr) * K + lhs;

    float c[4][4][4];
#pragma unroll
    for (int mf = 0; mf < 4; mf++)
#pragma unroll
        for (int nf = 0; nf < 4; nf++)
#pragma unroll
            for (int k = 0; k < 4; k++) c[mf][nf][k] = 0.f;

    // one ks-step of MMAs (16 HMMA) from buffer
    auto compute_ks = [&](const __half* Xs, const __half* Ws, int ks) {
        unsigned a[4][4], b[4][2];
        const int kc = ks * 16 + tg * 2;
#pragma unroll
        for (int mf = 0; mf < 4; mf++) {
            int row = wm * 64 + mf * 16;
            a[mf][0] = *(const unsigned*)&Xs[(row + g    ) * GSTR + kc    ];
            a[mf][1] = *(const unsigned*)&Xs[(row + g + 8) * GSTR + kc    ];
            a[mf][2] = *(const unsigned*)&Xs[(row + g    ) * GSTR + kc + 8];
            a[mf][3] = *(const unsigned*)&Xs[(row + g + 8) * GSTR + kc + 8];
        }
#pragma unroll
        for (int nf = 0; nf < 4; nf++) {
            int col = wn * 32 + nf * 8 + g;
            b[nf][0] = *(const unsigned*)&Ws[col * GSTR + kc    ];
            b[nf][1] = *(const unsigned*)&Ws[col * GSTR + kc + 8];
        }
#pragma unroll
        for (int mf = 0; mf < 4; mf++)
#pragma unroll
            for (int nf = 0; nf < 4; nf++)
                mma_f16(c[mf][nf], a[mf], b[nf]);
    };

    // full staging of chunk 0 (prologue, latency exposed once)
    {
        const uint4* xp = (const uint4*)(xg);
        const uint4* wp = (const uint4*)(wg);
        uint4* xs = (uint4*)(Xb[0] + lr * GSTR + lhs);
        uint4* ws = (uint4*)(Wb[0] + lr * GSTR + lhs);
        uint4 x0 = xp[0], x1 = xp[1], x2 = xp[2], x3 = xp[3];
        uint4 w0 = wp[0], w1 = wp[1], w2 = wp[2], w3 = wp[3];
        xs[0] = x0; xs[1] = x1; xs[2] = x2; xs[3] = x3;
        ws[0] = w0; ws[1] = w1; ws[2] = w2; ws[3] = w3;
    }
    __syncthreads();

    for (int ch = 0; ch < GEMM_NCH; ch++) {
        const int buf = ch & 1;
        const __half* Xs = Xb[buf];
        const __half* Ws = Wb[buf];
        const bool pf = (ch + 1 < GEMM_NCH);

        const uint4* xp = (const uint4*)(xg + (ch + 1) * GEMM_KC);
        const uint4* wp = (const uint4*)(wg + (ch + 1) * GEMM_KC);
        uint4* xs = (uint4*)(Xb[buf ^ 1] + lr * GSTR + lhs);
        uint4* ws = (uint4*)(Wb[buf ^ 1] + lr * GSTR + lhs);

        uint4 px0, px1, pw0, pw1;
        // batch 0 loads
        if (pf) { px0 = xp[0]; px1 = xp[1]; pw0 = wp[0]; pw1 = wp[1]; }
        // compute covers the LDG latency
        compute_ks(Xs, Ws, 0);
        compute_ks(Xs, Ws, 1);
        // batch 0 stores + batch 1 loads
        if (pf) {
            xs[0] = px0; xs[1] = px1; ws[0] = pw0; ws[1] = pw1;
            px0 = xp[2]; px1 = xp[3]; pw0 = wp[2]; pw1 = wp[3];
        }
        compute_ks(Xs, Ws, 2);
        compute_ks(Xs, Ws, 3);
        if (pf) {
            xs[2] = px0; xs[3] = px1; ws[2] = pw0; ws[3] = pw1;
        }
        __syncthreads();
    }

    // epilogue
#pragma unroll
    for (int mf = 0; mf < 4; mf++) {
#pragma unroll
        for (int nf = 0; nf < 4; nf++) {
            int row = bm + wm * 64 + mf * 16 + g;
            int col = bn + wn * 32 + nf * 8 + 2 * tg;
            float b0 = bias[col], b1 = bias[col + 1];
            float v0 = c[mf][nf][0] + b0, v1 = c[mf][nf][1] + b1;
            float v2 = c[mf][nf][2] + b0, v3 = c[mf][nf][3] + b1;
            if (OUT_MODE == 0) {
                float* Y = (float*)Yv;
                *(float2*)(Y + (size_t)row * N + col)       = make_float2(v0, v1);
                *(float2*)(Y + (size_t)(row + 8) * N + col) = make_float2(v2, v3);
            } else if (OUT_MODE == 1) {
                __half* Y = (__half*)Yv;
                *(__half2*)(Y + (size_t)row * N + col)       = __floats2half2_rn(v0, v1);
                *(__half2*)(Y + (size_t)(row + 8) * N + col) = __floats2half2_rn(v2, v3);
            } else {
                // per-head transpose: Yt[((b*16+h)*64 + d)][s]
                __half* Y = (__half*)Yv;
                int bb = row >> 11, s = row & (SEQ - 1);
                int h  = col >> 6,  d = col & 63;
                size_t r0 = ((size_t)(bb * N_HEADS + h) * DKH + d) * SEQ;
                Y[r0 + s]            = __float2half_rn(v0);
                Y[r0 + SEQ + s]      = __float2half_rn(v1);   // d+1
                Y[r0 + s + 8]        = __float2half_rn(v2);
                Y[r0 + SEQ + s + 8]  = __float2half_rn(v3);
            }
        }
    }
}

// Fused QKV projection: z=0 -> Q (fp16), z=1 -> K (fp16), z=2 -> V (fp16 transposed)
__global__ __launch_bounds__(256, 2)
void gemm_qkv_kernel(const __half* __restrict__ X0, const __half* __restrict__ X1,
                     const __half* __restrict__ X2,
                     const __half* __restrict__ W0, const __half* __restrict__ W1,
                     const __half* __restrict__ W2,
                     const float* __restrict__ b0, const float* __restrict__ b1,
                     const float* __restrict__ b2,
                     __half* __restrict__ Y0, __half* __restrict__ Y1,
                     __half* __restrict__ Y2)
{
    extern __shared__ __half gsm[];
    const int z = blockIdx.z;
    if (z == 2) {
        gemm_body<2>(X2, W2, b2, Y2, gsm);
    } else if (z == 1) {
        gemm_body<1>(X1, W1, b1, Y1, gsm);
    } else {
        gemm_body<1>(X0, W0, b0, Y0, gsm);
    }
}

// O-projection: fp32 output (final result).
__global__ __launch_bounds__(256, 2)
void gemm_one_kernel(const __half* __restrict__ X, const __half* __restrict__ W,
                     const float* __restrict__ bias, float* __restrict__ Y)
{
    extern __shared__ __half gsm[];
    gemm_body<0>(X, W, bias, Y, gsm);
}

// ---------------- flash attention, fp16 mma (BQ=64) --------------------------
// R14 version (cp.async staging — best measured). 128 thr / 4 warps.
#define PSTRH 72
#define KSTRH 72
#define VSTRH 72
#define FLASH_SMEM ((64 * PSTRH + 64 * KSTRH + 64 * VSTRH) * 2)   // 27648 B

__global__ __launch_bounds__(128, 4)
void flash_f16_kernel()
{
    extern __shared__ __half fsm[];
    __half* Ph  = fsm;                    // [64][PSTRH]  Q staging, then P
    __half* Kh  = Ph + 64 * PSTRH;        // [64][KSTRH]  K tile
    __half* Vth = Kh + 64 * KSTRH;        // [64][VSTRH]  Vt tile (row=d, col=key)

    const int tid  = threadIdx.x;
    const int warp = tid >> 5, lane = tid & 31;
    const int g = lane >> 2, tg = lane & 3;
    const int qt = (int)gridDim.x - 1 - (int)blockIdx.x;   // heavy blocks first
    const int bh = blockIdx.y;
    const int b  = bh >> 4, h = bh & 15;
    const int qbase = qt * 64;
    const int row0  = warp * 16;

    const size_t base  = (size_t)b * SEQ * D_MODEL + (size_t)h * DKH;
    const __half* Qg  = g_Qh + base;
    const __half* Kg  = g_Kh + base;
    const __half* Vtg = g_Vt + (size_t)(b * N_HEADS + h) * DKH * SEQ;

    const int sr = tid >> 3;          // staging row 0..15
    const int sc = (tid & 7) * 8;     // staging col (halves) 0..56

    const uint32_t phU = s2u(&Ph[sr * PSTRH + sc]);
    const uint32_t khU = s2u(&Kh[sr * KSTRH + sc]);
    const uint32_t vtU = s2u(&Vth[sr * VSTRH + sc]);

    // ---- stage Q via cp.async ----
#pragma unroll
    for (int p = 0; p < 4; p++) {
        int r = sr + 16 * p;
        cpa16(phU + (uint32_t)(16 * p * PSTRH * 2), Qg + (size_t)(qbase + r) * D_MODEL + sc);
    }
    asm volatile("cp.async.commit_group;" ::: "memory");
    asm volatile("cp.async.wait_group 0;" ::: "memory");
    __syncthreads();

    // ---- extract Q fragments (warp's 16 rows) ----
    unsigned qf[4][4];
#pragma unroll
    for (int ks = 0; ks < 4; ks++) {
        const int kc = ks * 16 + tg * 2;
        qf[ks][0] = *(const unsigned*)&Ph[(row0 + g    ) * PSTRH + kc    ];
        qf[ks][1] = *(const unsigned*)&Ph[(row0 + g + 8) * PSTRH + kc    ];
        qf[ks][2] = *(const unsigned*)&Ph[(row0 + g    ) * PSTRH + kc + 8];
        qf[ks][3] = *(const unsigned*)&Ph[(row0 + g + 8) * PSTRH + kc + 8];
    }

    float O[8][4];
#pragma unroll
    for (int nf = 0; nf < 8; nf++)
#pragma unroll
        for (int k = 0; k < 4; k++) O[nf][k] = 0.f;
    float m0 = -1e30f, m1 = -1e30f, l0 = 0.f, l1 = 0.f;

    const int q0r = qbase + row0 + g;
    const int q1r = q0r + 8;

    const int nkt = qt + 1;
    for (int kt = 0; kt < nkt; kt++) {
        const int kbase = kt * 64;
        __syncthreads();
        // ---- stage K and Vt via cp.async ----
#pragma unroll
        for (int p = 0; p < 4; p++) {
            int r = sr + 16 * p;
            cpa16(khU + (uint32_t)(16 * p * KSTRH * 2), Kg + (size_t)(kbase + r) * D_MODEL + sc);
            cpa16(vtU + (uint32_t)(16 * p * VSTRH * 2), Vtg + (size_t)r * SEQ + kbase + sc);
        }
        asm volatile("cp.async.commit_group;" ::: "memory");
        asm volatile("cp.async.wait_group 0;" ::: "memory");
        __syncthreads();

        // ---- S = Q K^T ----
        float S[8][4];
#pragma unroll
        for (int nf = 0; nf < 8; nf++)
#pragma unroll
            for (int k = 0; k < 4; k++) S[nf][k] = 0.f;

#pragma unroll
        for (int ks = 0; ks < 4; ks++) {
            const int kc = ks * 16 + tg * 2;
#pragma unroll
            for (int nf = 0; nf < 8; nf++) {
                unsigned bb[2];
                bb[0] = *(const unsigned*)&Kh[(nf * 8 + g) * KSTRH + kc    ];
                bb[1] = *(const unsigned*)&Kh[(nf * 8 + g) * KSTRH + kc + 8];
                mma_f16(S[nf], qf[ks], bb);
            }
        }

        // ---- scale + causal mask ----
        const bool diag = (kt == qt);
#pragma unroll
        for (int nf = 0; nf < 8; nf++) {
            int kc0 = kbase + nf * 8 + 2 * tg;
            S[nf][0] *= 0.125f; S[nf][1] *= 0.125f;
            S[nf][2] *= 0.125f; S[nf][3] *= 0.125f;
            if (diag) {
                if (kc0     > q0r) S[nf][0] = -1e30f;
                if (kc0 + 1 > q0r) S[nf][1] = -1e30f;
                if (kc0     > q1r) S[nf][2] = -1e30f;
                if (kc0 + 1 > q1r) S[nf][3] = -1e30f;
            }
        }

        // ---- online softmax ----
        float mx0 = -1e30f, mx1 = -1e30f;
#pragma unroll
        for (int nf = 0; nf < 8; nf++) {
            mx0 = fmaxf(mx0, fmaxf(S[nf][0], S[nf][1]));
            mx1 = fmaxf(mx1, fmaxf(S[nf][2], S[nf][3]));
        }
        mx0 = fmaxf(mx0, __shfl_xor_sync(0xffffffffu, mx0, 1));
        mx0 = fmaxf(mx0, __shfl_xor_sync(0xffffffffu, mx0, 2));
        mx1 = fmaxf(mx1, __shfl_xor_sync(0xffffffffu, mx1, 1));
        mx1 = fmaxf(mx1, __shfl_xor_sync(0xffffffffu, mx1, 2));

        float mn0 = fmaxf(m0, mx0), mn1 = fmaxf(m1, mx1);
        float fac0 = __expf(m0 - mn0), fac1 = __expf(m1 - mn1);

        float s0 = 0.f, s1 = 0.f;
#pragma unroll
        for (int nf = 0; nf < 8; nf++) {
            S[nf][0] = __expf(S[nf][0] - mn0);
            S[nf][1] = __expf(S[nf][1] - mn0);
            S[nf][2] = __expf(S[nf][2] - mn1);
            S[nf][3] = __expf(S[nf][3] - mn1);
            s0 += S[nf][0] + S[nf][1];
            s1 += S[nf][2] + S[nf][3];
        }
        s0 += __shfl_xor_sync(0xffffffffu, s0, 1);
        s0 += __shfl_xor_sync(0xffffffffu, s0, 2);
        s1 += __shfl_xor_sync(0xffffffffu, s1, 1);
        s1 += __shfl_xor_sync(0xffffffffu, s1, 2);

        l0 = l0 * fac0 + s0; l1 = l1 * fac1 + s1;
        m0 = mn0; m1 = mn1;
#pragma unroll
        for (int nf = 0; nf < 8; nf++) {
            O[nf][0] *= fac0; O[nf][1] *= fac0;
            O[nf][2] *= fac1; O[nf][3] *= fac1;
        }

        // ---- P -> smem fp16 (per-warp rows) ----
#pragma unroll
        for (int nf = 0; nf < 8; nf++) {
            int col = nf * 8 + 2 * tg;
            *(__half2*)&Ph[(row0 + g    ) * PSTRH + col] = __floats2half2_rn(S[nf][0], S[nf][1]);
            *(__half2*)&Ph[(row0 + g + 8) * PSTRH + col] = __floats2half2_rn(S[nf][2], S[nf][3]);
        }
        __syncwarp();

        // ---- O += P V ----
#pragma unroll
        for (int ks = 0; ks < 4; ks++) {
            const int kc = ks * 16 + tg * 2;
            unsigned a[4];
            a[0] = *(const unsigned*)&Ph[(row0 + g    ) * PSTRH + kc    ];
            a[1] = *(const unsigned*)&Ph[(row0 + g + 8) * PSTRH + kc    ];
            a[2] = *(const unsigned*)&Ph[(row0 + g    ) * PSTRH + kc + 8];
            a[3] = *(const unsigned*)&Ph[(row0 + g + 8) * PSTRH + kc + 8];
#pragma unroll
            for (int nf = 0; nf < 8; nf++) {
                unsigned bb[2];
                bb[0] = *(const unsigned*)&Vth[(nf * 8 + g) * VSTRH + kc    ];
                bb[1] = *(const unsigned*)&Vth[(nf * 8 + g) * VSTRH + kc + 8];
                mma_f16(O[nf], a, bb);
            }
        }
        __syncwarp();
    }

    // ---- normalize + write fp16 ----
    float inv0 = 1.0f / l0, inv1 = 1.0f / l1;
    __half* Ag = g_Ah + base;
#pragma unroll
    for (int nf = 0; nf < 8; nf++) {
        int col = nf * 8 + 2 * tg;
        *(__half2*)(Ag + (size_t)q0r * D_MODEL + col) =
            __floats2half2_rn(O[nf][0] * inv0, O[nf][1] * inv0);
        *(__half2*)(Ag + (size_t)q1r * D_MODEL + col) =
            __floats2half2_rn(O[nf][2] * inv1, O[nf][3] * inv1);
    }
}

// ---------------- launch -----------------------------------------------------
extern "C" void kernel_launch(void* const* d_in, const int* in_sizes, int n_in,
                              void* d_out, int out_size)
{
    (void)in_sizes; (void)n_in; (void)out_size;
    const float* in_Q = (const float*)d_in[0];
    const float* in_K = (const float*)d_in[1];
    const float* in_V = (const float*)d_in[2];
    const float* Wq   = (const float*)d_in[3];
    const float* bq   = (const float*)d_in[4];
    const float* Wk   = (const float*)d_in[5];
    const float* bk   = (const float*)d_in[6];
    const float* Wv   = (const float*)d_in[7];
    const float* bv   = (const float*)d_in[8];
    const float* Wo   = (const float*)d_in[9];
    const float* bo   = (const float*)d_in[10];
    float* out = (float*)d_out;

    __half *qh, *kh, *vt, *ah, *xq, *xk, *xv, *wq, *wk, *wv, *wo;
    cudaGetSymbolAddress((void**)&qh, g_Qh);
    cudaGetSymbolAddress((void**)&kh, g_Kh);
    cudaGetSymbolAddress((void**)&vt, g_Vt);
    cudaGetSymbolAddress((void**)&ah, g_Ah);
    cudaGetSymbolAddress((void**)&xq, g_Xq);
    cudaGetSymbolAddress((void**)&xk, g_Xk);
    cudaGetSymbolAddress((void**)&xv, g_Xv);
    cudaGetSymbolAddress((void**)&wq, g_Wq);
    cudaGetSymbolAddress((void**)&wk, g_Wk);
    cudaGetSymbolAddress((void**)&wv, g_Wv);
    cudaGetSymbolAddress((void**)&wo, g_Wo);

    cudaFuncSetAttribute(gemm_qkv_kernel,
                         cudaFuncAttributeMaxDynamicSharedMemorySize, GEMM_SMEM);
    cudaFuncSetAttribute(gemm_one_kernel,
                         cudaFuncAttributeMaxDynamicSharedMemorySize, GEMM_SMEM);
    cudaFuncSetAttribute(flash_f16_kernel,
                         cudaFuncAttributeMaxDynamicSharedMemorySize, FLASH_SMEM);

    // 1) convert inputs + weights to fp16
    dim3 pc_grid(1024, 1, 7);
    preconv_kernel<<<pc_grid, 256>>>(in_Q, in_K, in_V, Wq, Wk, Wv, Wo,
                                     xq, xk, xv, wq, wk, wv, wo);

    // 2) fused QKV projections (fp16 outputs; V transposed per head)
    dim3 qkv_grid(D_MODEL / 128, M_TOT / 128, 3);   // (8, 32, 3)
    gemm_qkv_kernel<<<qkv_grid, 256, GEMM_SMEM>>>(
        xq, xk, xv, wq, wk, wv, bq, bk, bv, qh, kh, vt);

    // 3) flash attention (fp16; writes fp16 g_Ah)
    dim3 fgrid(SEQ / 64, BATCH * N_HEADS);          // (32, 32)
    flash_f16_kernel<<<fgrid, 128, FLASH_SMEM>>>();

    // 4) output projection (fp16 mma, fp32 result)
    dim3 o_grid(D_MODEL / 128, M_TOT / 128);        // (8, 32)
    gemm_one_kernel<<<o_grid, 256, GEMM_SMEM>>>(ah, wo, bo, out);
}